// round 14
// baseline (speedup 1.0000x reference)
#include <cuda_runtime.h>
#include <cuda_bf16.h>
#include <math.h>
#include <stdint.h>

#define NN 100000
#define NE 400000
#define DIM 512

#define SCAN_BLK 1024
#define SCAN_NBLK ((NN + SCAN_BLK - 1) / SCAN_BLK)   // 98

// ---------------- scratch (static device globals; no allocations) -----------
__device__ __align__(16) uint16_t g_bufA[(size_t)NN * DIM];
__device__ __align__(16) uint16_t g_bufG[(size_t)NN * DIM];
__device__ float g_dinv[NN];
__device__ float g_scal[NN];
__device__ float g_wvec[(size_t)NN * 4];   // N x 3 class weights (padded to 4)
__device__ float g_M1[3 * DIM];            // emb @ W1
__device__ int   g_cnt[NN];
__device__ int   g_cur[NN];
__device__ int   g_off[NN + 1];
__device__ int   g_bsum[SCAN_NBLK + 1];
__device__ int   g_csrc[NE];

// ---------------- helpers ----------------------------------------------------
__device__ __forceinline__ uint32_t pack_bf16x2(float lo, float hi) {
    __nv_bfloat162 h = __floats2bfloat162_rn(lo, hi);
    return *(uint32_t*)&h;
}
__device__ __forceinline__ float2 unpack_bf16x2(uint32_t u) {
    __nv_bfloat162 h = *(__nv_bfloat162*)&u;
    return __bfloat1622float2(h);
}

__device__ __forceinline__ void ldsm_x4(uint32_t& r0, uint32_t& r1, uint32_t& r2,
                                        uint32_t& r3, uint32_t addr) {
    asm volatile("ldmatrix.sync.aligned.m8n8.x4.shared.b16 {%0,%1,%2,%3}, [%4];"
                 : "=r"(r0), "=r"(r1), "=r"(r2), "=r"(r3) : "r"(addr));
}
__device__ __forceinline__ void ldsm_x4_t(uint32_t& r0, uint32_t& r1, uint32_t& r2,
                                          uint32_t& r3, uint32_t addr) {
    asm volatile("ldmatrix.sync.aligned.m8n8.x4.trans.shared.b16 {%0,%1,%2,%3}, [%4];"
                 : "=r"(r0), "=r"(r1), "=r"(r2), "=r"(r3) : "r"(addr));
}
__device__ __forceinline__ void mma_bf16(float* c, const uint32_t* a,
                                         uint32_t b0, uint32_t b1) {
    asm volatile(
        "mma.sync.aligned.m16n8k16.row.col.f32.bf16.bf16.f32 "
        "{%0,%1,%2,%3}, {%4,%5,%6,%7}, {%8,%9}, {%0,%1,%2,%3};"
        : "+f"(c[0]), "+f"(c[1]), "+f"(c[2]), "+f"(c[3])
        : "r"(a[0]), "r"(a[1]), "r"(a[2]), "r"(a[3]), "r"(b0), "r"(b1));
}

// ---------------- graph preprocessing ---------------------------------------
__global__ void k_count(const int* __restrict__ dst, int E) {
    int e = blockIdx.x * blockDim.x + threadIdx.x;
    if (e < E) atomicAdd(&g_cnt[dst[e]], 1);
}

__global__ void k_scan1(int n) {
    __shared__ int wsum[32];
    int tid = threadIdx.x, lane = tid & 31, wid = tid >> 5;
    int i = blockIdx.x * SCAN_BLK + tid;
    int v = (i < n) ? g_cnt[i] : 0;
    if (i < n) g_dinv[i] = rsqrtf((float)(v + 1));
    int incl = v;
    #pragma unroll
    for (int o = 1; o < 32; o <<= 1) {
        int t = __shfl_up_sync(0xFFFFFFFFu, incl, o);
        if (lane >= o) incl += t;
    }
    if (lane == 31) wsum[wid] = incl;
    __syncthreads();
    if (wid == 0) {
        int s = wsum[lane];
        int si = s;
        #pragma unroll
        for (int o = 1; o < 32; o <<= 1) {
            int t = __shfl_up_sync(0xFFFFFFFFu, si, o);
            if (lane >= o) si += t;
        }
        wsum[lane] = si - s;
        if (lane == 31) g_bsum[blockIdx.x] = si;   // block total
    }
    __syncthreads();
    if (i < n) g_off[i] = wsum[wid] + incl - v;
}

__global__ void k_scan2(int n) {
    int tid = threadIdx.x;   // 128 threads
    __shared__ int ws[4];
    int lane = tid & 31, wid = tid >> 5;
    int v = (tid < SCAN_NBLK) ? g_bsum[tid] : 0;
    int incl = v;
    #pragma unroll
    for (int o = 1; o < 32; o <<= 1) {
        int t = __shfl_up_sync(0xFFFFFFFFu, incl, o);
        if (lane >= o) incl += t;
    }
    if (lane == 31) ws[wid] = incl;
    __syncthreads();
    int woff = 0;
    #pragma unroll
    for (int k = 0; k < 4; ++k) woff += (k < wid) ? ws[k] : 0;
    if (tid < SCAN_NBLK) g_bsum[tid] = woff + incl - v;   // exclusive
    if (tid == 127) g_off[n] = woff + incl;               // grand total = NE
}

__global__ void k_scan3(int n) {
    int i = blockIdx.x * blockDim.x + threadIdx.x;
    if (i < n) g_off[i] += g_bsum[i >> 10];
}

__global__ void k_fill(const int* __restrict__ src, const int* __restrict__ dst, int E) {
    int e = blockIdx.x * blockDim.x + threadIdx.x;
    if (e < E) {
        int d = dst[e];
        int p = g_off[d] + atomicAdd(&g_cur[d], 1);
        g_csrc[p] = src[e];
    }
}

// ---------------- layer 1 (rank-3 path) --------------------------------------
__global__ void k_m1(const float* __restrict__ emb, const float* __restrict__ W1) {
    int r = blockIdx.x;            // 0..2
    int c = threadIdx.x;           // 0..511
    const float* er = emb + r * DIM;
    float acc = 0.f;
    for (int k = 0; k < DIM; ++k) acc = fmaf(er[k], W1[(size_t)k * DIM + c], acc);
    g_M1[r * DIM + c] = acc;
}

__global__ void k_wvec(const int* __restrict__ x, int n) {
    int d = blockIdx.x * blockDim.x + threadIdx.x;
    if (d >= n) return;
    float dv = g_dinv[d];
    float w[3] = {0.f, 0.f, 0.f};
    int e0 = g_off[d], e1 = g_off[d + 1];
    for (int e = e0; e < e1; ++e) {
        int s = g_csrc[e];
        w[x[s]] += g_dinv[s];
    }
    w[x[d]] += dv;
    float4 o;
    o.x = dv * w[0]; o.y = dv * w[1]; o.z = dv * w[2]; o.w = 0.f;
    *(float4*)&g_wvec[4 * (size_t)d] = o;
}

// ---------------- GEMM common pieces -----------------------------------------
#define BM 128
#define BN 128
#define BK 16
#define APITCHB 48
#define BPITCHB 272

// Fused layer-1 + GEMM-2: G = (relu(wvec@M1 + b1) @ W) * dinv[row]
__global__ void __launch_bounds__(256, 2)
k_gemm_l1(const float* __restrict__ W, const float* __restrict__ b1,
          uint16_t* __restrict__ G, int M) {
    __shared__ __align__(16) char As[2][BM * APITCHB];
    __shared__ __align__(16) char Bs[2][BK * BPITCHB];
    __shared__ float sM1[3][DIM];
    __shared__ float sB1[DIM];

    const int tid = threadIdx.x;
    const int lane = tid & 31;
    const int gid = lane >> 2;
    const int tig = lane & 3;
    const int warpId = tid >> 5;
    const int m0 = (warpId & 3) * 32;
    const int n0 = (warpId >> 2) * 64;

    const int rowBase = blockIdx.y * BM;
    const int colBase = blockIdx.x * BN;

    const int ar = tid >> 1;
    const int ah = tid & 1;
    const int arow = rowBase + ar;
    const bool aok = (arow < M);

    const int brow = tid >> 4;
    const int bc8 = (tid & 15) * 8;

    for (int i = tid; i < 3 * DIM; i += 256) ((float*)sM1)[i] = g_M1[i];
    for (int i = tid; i < DIM; i += 256) sB1[i] = b1[i];

    uint32_t asb[2], bsb[2];
    asb[0] = (uint32_t)__cvta_generic_to_shared(As[0]);
    asb[1] = (uint32_t)__cvta_generic_to_shared(As[1]);
    bsb[0] = (uint32_t)__cvta_generic_to_shared(Bs[0]);
    bsb[1] = (uint32_t)__cvta_generic_to_shared(Bs[1]);

    const uint32_t aoff = (uint32_t)(lane & 15) * APITCHB + (uint32_t)(lane >> 4) * 16;
    const uint32_t boff = (uint32_t)(lane & 15) * BPITCHB + (uint32_t)(lane >> 4) * 16;

    float4 wv = make_float4(0.f, 0.f, 0.f, 0.f);
    if (aok) wv = *(const float4*)&g_wvec[4 * (size_t)arow];

    float acc[2][8][4];
    #pragma unroll
    for (int i = 0; i < 2; ++i)
        #pragma unroll
        for (int j = 0; j < 8; ++j)
            #pragma unroll
            for (int k = 0; k < 4; ++k) acc[i][j][k] = 0.f;

    float4 pb0, pb1;
    {
        const float* wr = W + (size_t)brow * DIM + colBase + bc8;
        pb0 = *(const float4*)wr;
        pb1 = *(const float4*)(wr + 4);
    }
    __syncthreads();   // sM1/sB1 ready

    {
        int kb = ah * 8;
        float r[8];
        #pragma unroll
        for (int i = 0; i < 8; ++i) {
            float v = wv.x * sM1[0][kb + i] + wv.y * sM1[1][kb + i]
                    + wv.z * sM1[2][kb + i] + sB1[kb + i];
            r[i] = aok ? fmaxf(v, 0.f) : 0.f;
        }
        uint4 o;
        o.x = pack_bf16x2(r[0], r[1]);
        o.y = pack_bf16x2(r[2], r[3]);
        o.z = pack_bf16x2(r[4], r[5]);
        o.w = pack_bf16x2(r[6], r[7]);
        *(uint4*)(As[0] + ar * APITCHB + ah * 16) = o;
        uint4 v;
        v.x = pack_bf16x2(pb0.x, pb0.y);
        v.y = pack_bf16x2(pb0.z, pb0.w);
        v.z = pack_bf16x2(pb1.x, pb1.y);
        v.w = pack_bf16x2(pb1.z, pb1.w);
        *(uint4*)(Bs[0] + brow * BPITCHB + bc8 * 2) = v;
    }
    __syncthreads();

    const int NT = DIM / BK;
    int buf = 0;
    for (int t = 0; t < NT; ++t) {
        if (t + 1 < NT) {
            int k0 = (t + 1) * BK;
            const float* wr = W + (size_t)(k0 + brow) * DIM + colBase + bc8;
            pb0 = *(const float4*)wr;
            pb1 = *(const float4*)(wr + 4);
        }

        uint32_t af[2][4];
        #pragma unroll
        for (int mf = 0; mf < 2; ++mf)
            ldsm_x4(af[mf][0], af[mf][1], af[mf][2], af[mf][3],
                    asb[buf] + (uint32_t)(m0 + mf * 16) * APITCHB + aoff);

        #pragma unroll
        for (int p = 0; p < 4; ++p) {
            uint32_t b0, b1r, b2, b3;
            ldsm_x4_t(b0, b1r, b2, b3,
                      bsb[buf] + boff + (uint32_t)(n0 + p * 16) * 2);
            #pragma unroll
            for (int mf = 0; mf < 2; ++mf) {
                mma_bf16(acc[mf][2 * p],     af[mf], b0, b1r);
                mma_bf16(acc[mf][2 * p + 1], af[mf], b2, b3);
            }
        }

        if (t + 1 < NT) {
            buf ^= 1;
            int kb = (t + 1) * BK + ah * 8;
            float r[8];
            #pragma unroll
            for (int i = 0; i < 8; ++i) {
                float v = wv.x * sM1[0][kb + i] + wv.y * sM1[1][kb + i]
                        + wv.z * sM1[2][kb + i] + sB1[kb + i];
                r[i] = aok ? fmaxf(v, 0.f) : 0.f;
            }
            uint4 o;
            o.x = pack_bf16x2(r[0], r[1]);
            o.y = pack_bf16x2(r[2], r[3]);
            o.z = pack_bf16x2(r[4], r[5]);
            o.w = pack_bf16x2(r[6], r[7]);
            *(uint4*)(As[buf] + ar * APITCHB + ah * 16) = o;
            uint4 v;
            v.x = pack_bf16x2(pb0.x, pb0.y);
            v.y = pack_bf16x2(pb0.z, pb0.w);
            v.z = pack_bf16x2(pb1.x, pb1.y);
            v.w = pack_bf16x2(pb1.z, pb1.w);
            *(uint4*)(Bs[buf] + brow * BPITCHB + bc8 * 2) = v;
            __syncthreads();
        }
    }

    #pragma unroll
    for (int mf = 0; mf < 2; ++mf) {
        int r = rowBase + m0 + mf * 16 + gid;
        float dv0 = (r < M) ? g_dinv[r] : 0.f;
        float dv1 = (r + 8 < M) ? g_dinv[r + 8] : 0.f;
        #pragma unroll
        for (int nf = 0; nf < 8; ++nf) {
            int c = colBase + n0 + nf * 8 + 2 * tig;
            if (r < M)
                *(uint32_t*)(G + (size_t)r * DIM + c) =
                    pack_bf16x2(acc[mf][nf][0] * dv0, acc[mf][nf][1] * dv0);
            if (r + 8 < M)
                *(uint32_t*)(G + (size_t)(r + 8) * DIM + c) =
                    pack_bf16x2(acc[mf][nf][2] * dv1, acc[mf][nf][3] * dv1);
        }
    }
}

// Generic GEMM (layer 3): G = (A @ W) * dinv[row]
__global__ void __launch_bounds__(256, 2)
k_gemm(const uint16_t* __restrict__ A, const float* __restrict__ W,
       uint16_t* __restrict__ G, int M) {
    __shared__ __align__(16) char As[2][BM * APITCHB];
    __shared__ __align__(16) char Bs[2][BK * BPITCHB];

    const int tid = threadIdx.x;
    const int lane = tid & 31;
    const int gid = lane >> 2;
    const int tig = lane & 3;
    const int warpId = tid >> 5;
    const int m0 = (warpId & 3) * 32;
    const int n0 = (warpId >> 2) * 64;

    const int rowBase = blockIdx.y * BM;
    const int colBase = blockIdx.x * BN;

    const int ar = tid >> 1;
    const int ah = tid & 1;
    const int arow = rowBase + ar;
    const bool aok = (arow < M);
    const uint4* Ag = (const uint4*)(A + (size_t)arow * DIM);

    const int brow = tid >> 4;
    const int bc8 = (tid & 15) * 8;

    uint32_t asb[2], bsb[2];
    asb[0] = (uint32_t)__cvta_generic_to_shared(As[0]);
    asb[1] = (uint32_t)__cvta_generic_to_shared(As[1]);
    bsb[0] = (uint32_t)__cvta_generic_to_shared(Bs[0]);
    bsb[1] = (uint32_t)__cvta_generic_to_shared(Bs[1]);

    const uint32_t aoff = (uint32_t)(lane & 15) * APITCHB + (uint32_t)(lane >> 4) * 16;
    const uint32_t boff = (uint32_t)(lane & 15) * BPITCHB + (uint32_t)(lane >> 4) * 16;

    float acc[2][8][4];
    #pragma unroll
    for (int i = 0; i < 2; ++i)
        #pragma unroll
        for (int j = 0; j < 8; ++j)
            #pragma unroll
            for (int k = 0; k < 4; ++k) acc[i][j][k] = 0.f;

    uint4 pa;
    float4 pb0, pb1;

    pa = aok ? Ag[ah] : make_uint4(0, 0, 0, 0);
    {
        const float* wr = W + (size_t)brow * DIM + colBase + bc8;
        pb0 = *(const float4*)wr;
        pb1 = *(const float4*)(wr + 4);
    }
    *(uint4*)(As[0] + ar * APITCHB + ah * 16) = pa;
    {
        uint4 v;
        v.x = pack_bf16x2(pb0.x, pb0.y);
        v.y = pack_bf16x2(pb0.z, pb0.w);
        v.z = pack_bf16x2(pb1.x, pb1.y);
        v.w = pack_bf16x2(pb1.z, pb1.w);
        *(uint4*)(Bs[0] + brow * BPITCHB + bc8 * 2) = v;
    }
    __syncthreads();

    const int NT = DIM / BK;
    int buf = 0;
    for (int t = 0; t < NT; ++t) {
        if (t + 1 < NT) {
            int k0 = (t + 1) * BK;
            pa = aok ? Ag[(k0 >> 3) + ah] : make_uint4(0, 0, 0, 0);
            const float* wr = W + (size_t)(k0 + brow) * DIM + colBase + bc8;
            pb0 = *(const float4*)wr;
            pb1 = *(const float4*)(wr + 4);
        }

        uint32_t af[2][4];
        #pragma unroll
        for (int mf = 0; mf < 2; ++mf)
            ldsm_x4(af[mf][0], af[mf][1], af[mf][2], af[mf][3],
                    asb[buf] + (uint32_t)(m0 + mf * 16) * APITCHB + aoff);

        #pragma unroll
        for (int p = 0; p < 4; ++p) {
            uint32_t b0, b1, b2, b3;
            ldsm_x4_t(b0, b1, b2, b3,
                      bsb[buf] + boff + (uint32_t)(n0 + p * 16) * 2);
            #pragma unroll
            for (int mf = 0; mf < 2; ++mf) {
                mma_bf16(acc[mf][2 * p],     af[mf], b0, b1);
                mma_bf16(acc[mf][2 * p + 1], af[mf], b2, b3);
            }
        }

        if (t + 1 < NT) {
            buf ^= 1;
            *(uint4*)(As[buf] + ar * APITCHB + ah * 16) = pa;
            uint4 v;
            v.x = pack_bf16x2(pb0.x, pb0.y);
            v.y = pack_bf16x2(pb0.z, pb0.w);
            v.z = pack_bf16x2(pb1.x, pb1.y);
            v.w = pack_bf16x2(pb1.z, pb1.w);
            *(uint4*)(Bs[buf] + brow * BPITCHB + bc8 * 2) = v;
            __syncthreads();
        }
    }

    #pragma unroll
    for (int mf = 0; mf < 2; ++mf) {
        int r = rowBase + m0 + mf * 16 + gid;
        float dv0 = (r < M) ? g_dinv[r] : 0.f;
        float dv1 = (r + 8 < M) ? g_dinv[r + 8] : 0.f;
        #pragma unroll
        for (int nf = 0; nf < 8; ++nf) {
            int c = colBase + n0 + nf * 8 + 2 * tig;
            if (r < M)
                *(uint32_t*)(G + (size_t)r * DIM + c) =
                    pack_bf16x2(acc[mf][nf][0] * dv0, acc[mf][nf][1] * dv0);
            if (r + 8 < M)
                *(uint32_t*)(G + (size_t)(r + 8) * DIM + c) =
                    pack_bf16x2(acc[mf][nf][2] * dv1, acc[mf][nf][3] * dv1);
        }
    }
}

// ---------------- aggregation (layer 2): 64 threads per node ------------------
// Each thread owns ONE uint4 (8 cols) of the node's row; per edge it issues a
// single independent 16B load — shorter dependency chain, low register count.
__global__ void k_agg(const uint16_t* __restrict__ G, const float* __restrict__ bias,
                      uint16_t* __restrict__ out, int n, int do_relu) {
    int w = (blockIdx.x * blockDim.x + threadIdx.x) >> 6;   // node
    int l = threadIdx.x & 63;                               // uint4 slot 0..63
    if (w >= n) return;
    const uint4* G4 = (const uint4*)G;
    size_t base = (size_t)w * 64;

    float acc[8];
    {
        uint4 v = G4[base + l];
        float2 f;
        f = unpack_bf16x2(v.x); acc[0] = f.x; acc[1] = f.y;
        f = unpack_bf16x2(v.y); acc[2] = f.x; acc[3] = f.y;
        f = unpack_bf16x2(v.z); acc[4] = f.x; acc[5] = f.y;
        f = unpack_bf16x2(v.w); acc[6] = f.x; acc[7] = f.y;
    }
    int e0 = g_off[w], e1 = g_off[w + 1];
    for (int e = e0; e < e1; ++e) {
        uint4 v = G4[(size_t)g_csrc[e] * 64 + l];
        float2 f;
        f = unpack_bf16x2(v.x); acc[0] += f.x; acc[1] += f.y;
        f = unpack_bf16x2(v.y); acc[2] += f.x; acc[3] += f.y;
        f = unpack_bf16x2(v.z); acc[4] += f.x; acc[5] += f.y;
        f = unpack_bf16x2(v.w); acc[6] += f.x; acc[7] += f.y;
    }
    float d = g_dinv[w];
    const float4* B4 = (const float4*)bias;
    float4 bb0 = B4[2 * l], bb1 = B4[2 * l + 1];
    float r[8];
    r[0] = acc[0] * d + bb0.x;
    r[1] = acc[1] * d + bb0.y;
    r[2] = acc[2] * d + bb0.z;
    r[3] = acc[3] * d + bb0.w;
    r[4] = acc[4] * d + bb1.x;
    r[5] = acc[5] * d + bb1.y;
    r[6] = acc[6] * d + bb1.z;
    r[7] = acc[7] * d + bb1.w;
    if (do_relu) {
        #pragma unroll
        for (int i = 0; i < 8; ++i) r[i] = fmaxf(r[i], 0.f);
    }
    uint4 v;
    v.x = pack_bf16x2(r[0], r[1]);
    v.y = pack_bf16x2(r[2], r[3]);
    v.z = pack_bf16x2(r[4], r[5]);
    v.w = pack_bf16x2(r[6], r[7]);
    ((uint4*)out)[base + l] = v;
}

// ---------------- layer-3 aggregation fused with layer-4 dot ------------------
// Same 64-threads-per-node layout; cross-warp pair reduction via smem.
__global__ void k_agg_dot(const uint16_t* __restrict__ G, const float* __restrict__ b3,
                          const float* __restrict__ W4, int n) {
    __shared__ float sW4[DIM];
    __shared__ float sB3[DIM];
    __shared__ float part[8];   // one partial per warp (8 warps)
    int tid = threadIdx.x;
    for (int i = tid; i < DIM; i += blockDim.x) { sW4[i] = W4[i]; sB3[i] = b3[i]; }
    __syncthreads();

    int w = (blockIdx.x * blockDim.x + tid) >> 6;
    int l = tid & 63;
    int lane = tid & 31, wid = tid >> 5;
    bool ok = (w < n);

    float s = 0.f;
    float d = 0.f;
    if (ok) {
        const uint4* G4 = (const uint4*)G;
        size_t base = (size_t)w * 64;
        float acc[8];
        {
            uint4 v = G4[base + l];
            float2 f;
            f = unpack_bf16x2(v.x); acc[0] = f.x; acc[1] = f.y;
            f = unpack_bf16x2(v.y); acc[2] = f.x; acc[3] = f.y;
            f = unpack_bf16x2(v.z); acc[4] = f.x; acc[5] = f.y;
            f = unpack_bf16x2(v.w); acc[6] = f.x; acc[7] = f.y;
        }
        int e0 = g_off[w], e1 = g_off[w + 1];
        for (int e = e0; e < e1; ++e) {
            uint4 v = G4[(size_t)g_csrc[e] * 64 + l];
            float2 f;
            f = unpack_bf16x2(v.x); acc[0] += f.x; acc[1] += f.y;
            f = unpack_bf16x2(v.y); acc[2] += f.x; acc[3] += f.y;
            f = unpack_bf16x2(v.z); acc[4] += f.x; acc[5] += f.y;
            f = unpack_bf16x2(v.w); acc[6] += f.x; acc[7] += f.y;
        }
        d = g_dinv[w];
        int c = 8 * l;
        #pragma unroll
        for (int i = 0; i < 8; ++i) {
            float h = fmaxf(acc[i] * d + sB3[c + i], 0.f);
            s = fmaf(h, sW4[c + i], s);
        }
    }
    #pragma unroll
    for (int o = 16; o > 0; o >>= 1) s += __shfl_xor_sync(0xFFFFFFFFu, s, o);
    if (lane == 0) part[wid] = s;
    __syncthreads();
    if (ok && l == 0)
        g_scal[w] = (part[wid] + part[wid + 1]) * d;
}

__global__ void k_agg4(const float* __restrict__ b4, float* __restrict__ out, int n) {
    int i = blockIdx.x * blockDim.x + threadIdx.x;
    if (i >= n) return;
    float a = g_scal[i];
    int e0 = g_off[i], e1 = g_off[i + 1];
    for (int e = e0; e < e1; ++e) a += g_scal[g_csrc[e]];
    float v = g_dinv[i] * a + b4[0];
    out[i] = 1.f / (1.f + expf(-v));
}

// ---------------- launcher ---------------------------------------------------
extern "C" void kernel_launch(void* const* d_in, const int* in_sizes, int n_in,
                              void* d_out, int out_size) {
    const int*   x   = (const int*)d_in[0];
    const int*   ei  = (const int*)d_in[1];
    const float* emb = (const float*)d_in[2];
    const float* W1  = (const float*)d_in[3];
    const float* b1  = (const float*)d_in[4];
    const float* W2  = (const float*)d_in[5];
    const float* b2  = (const float*)d_in[6];
    const float* W3  = (const float*)d_in[7];
    const float* b3  = (const float*)d_in[8];
    const float* W4  = (const float*)d_in[9];
    const float* b4  = (const float*)d_in[10];
    float* out = (float*)d_out;

    int N = in_sizes[0];
    int E = in_sizes[1] / 2;
    const int* src = ei;
    const int* dst = ei + E;

    uint16_t *bufA, *bufG;
    cudaGetSymbolAddress((void**)&bufA, g_bufA);
    cudaGetSymbolAddress((void**)&bufG, g_bufG);
    int *cntp, *curp;
    cudaGetSymbolAddress((void**)&cntp, g_cnt);
    cudaGetSymbolAddress((void**)&curp, g_cur);

    // graph preprocessing
    cudaMemsetAsync(cntp, 0, (size_t)N * sizeof(int));
    cudaMemsetAsync(curp, 0, (size_t)N * sizeof(int));
    k_count<<<(E + 255) / 256, 256>>>(dst, E);
    k_m1   <<<3, DIM>>>(emb, W1);
    k_scan1<<<SCAN_NBLK, SCAN_BLK>>>(N);
    k_scan2<<<1, 128>>>(N);
    k_scan3<<<(N + 1023) / 1024, 1024>>>(N);
    k_fill <<<(E + 255) / 256, 256>>>(src, dst, E);
    k_wvec <<<(N + 255) / 256, 256>>>(x, N);

    dim3 ggrid(DIM / BN, (N + BM - 1) / BM);
    int aggBlocks = (N + 3) / 4;   // 64 threads per node, 256-thread blocks

    // layer 1+2 fused GEMM, then aggregation
    k_gemm_l1<<<ggrid, 256>>>(W2, b1, bufG, N);
    k_agg    <<<aggBlocks, 256>>>(bufG, b2, bufA, N, 1);
    // layer 3 GEMM, then aggregation fused with layer-4 dot
    k_gemm   <<<ggrid, 256>>>(bufA, W3, bufG, N);
    k_agg_dot<<<aggBlocks, 256>>>(bufG, b3, W4, N);
    // layer 4 scalar aggregation + sigmoid
    k_agg4   <<<(N + 255) / 256, 256>>>(b4, out, N);
}

// round 15
// speedup vs baseline: 1.0298x; 1.0298x over previous
#include <cuda_runtime.h>
#include <cuda_bf16.h>
#include <math.h>
#include <stdint.h>

#define NN 100000
#define NE 400000
#define DIM 512

#define SCAN_BLK 1024
#define SCAN_NBLK ((NN + SCAN_BLK - 1) / SCAN_BLK)   // 98

// ---------------- scratch (static device globals; no allocations) -----------
__device__ __align__(16) uint16_t g_bufA[(size_t)NN * DIM];
__device__ __align__(16) uint16_t g_bufG[(size_t)NN * DIM];
__device__ float g_dinv[NN];
__device__ float g_scal[NN];
__device__ float g_wvec[(size_t)NN * 4];   // N x 3 class weights (padded to 4)
__device__ float g_M1[3 * DIM];            // emb @ W1
__device__ int   g_cnt[NN];
__device__ int   g_cur[NN];
__device__ int   g_off[NN + 1];
__device__ int   g_bsum[SCAN_NBLK + 1];
__device__ int   g_csrc[NE];

// ---------------- helpers ----------------------------------------------------
__device__ __forceinline__ uint32_t pack_bf16x2(float lo, float hi) {
    __nv_bfloat162 h = __floats2bfloat162_rn(lo, hi);
    return *(uint32_t*)&h;
}
__device__ __forceinline__ float2 unpack_bf16x2(uint32_t u) {
    __nv_bfloat162 h = *(__nv_bfloat162*)&u;
    return __bfloat1622float2(h);
}

__device__ __forceinline__ void ldsm_x4(uint32_t& r0, uint32_t& r1, uint32_t& r2,
                                        uint32_t& r3, uint32_t addr) {
    asm volatile("ldmatrix.sync.aligned.m8n8.x4.shared.b16 {%0,%1,%2,%3}, [%4];"
                 : "=r"(r0), "=r"(r1), "=r"(r2), "=r"(r3) : "r"(addr));
}
__device__ __forceinline__ void ldsm_x4_t(uint32_t& r0, uint32_t& r1, uint32_t& r2,
                                          uint32_t& r3, uint32_t addr) {
    asm volatile("ldmatrix.sync.aligned.m8n8.x4.trans.shared.b16 {%0,%1,%2,%3}, [%4];"
                 : "=r"(r0), "=r"(r1), "=r"(r2), "=r"(r3) : "r"(addr));
}
__device__ __forceinline__ void mma_bf16(float* c, const uint32_t* a,
                                         uint32_t b0, uint32_t b1) {
    asm volatile(
        "mma.sync.aligned.m16n8k16.row.col.f32.bf16.bf16.f32 "
        "{%0,%1,%2,%3}, {%4,%5,%6,%7}, {%8,%9}, {%0,%1,%2,%3};"
        : "+f"(c[0]), "+f"(c[1]), "+f"(c[2]), "+f"(c[3])
        : "r"(a[0]), "r"(a[1]), "r"(a[2]), "r"(a[3]), "r"(b0), "r"(b1));
}

// ---------------- graph preprocessing ---------------------------------------
__global__ void k_count(const int* __restrict__ dst, int E) {
    int e = blockIdx.x * blockDim.x + threadIdx.x;
    if (e < E) atomicAdd(&g_cnt[dst[e]], 1);
}

__global__ void k_scan1(int n) {
    __shared__ int wsum[32];
    int tid = threadIdx.x, lane = tid & 31, wid = tid >> 5;
    int i = blockIdx.x * SCAN_BLK + tid;
    int v = (i < n) ? g_cnt[i] : 0;
    if (i < n) { g_dinv[i] = rsqrtf((float)(v + 1)); g_cur[i] = 0; }
    int incl = v;
    #pragma unroll
    for (int o = 1; o < 32; o <<= 1) {
        int t = __shfl_up_sync(0xFFFFFFFFu, incl, o);
        if (lane >= o) incl += t;
    }
    if (lane == 31) wsum[wid] = incl;
    __syncthreads();
    if (wid == 0) {
        int s = wsum[lane];
        int si = s;
        #pragma unroll
        for (int o = 1; o < 32; o <<= 1) {
            int t = __shfl_up_sync(0xFFFFFFFFu, si, o);
            if (lane >= o) si += t;
        }
        wsum[lane] = si - s;
        if (lane == 31) g_bsum[blockIdx.x] = si;   // block total
    }
    __syncthreads();
    if (i < n) g_off[i] = wsum[wid] + incl - v;
}

__global__ void k_scan2(int n) {
    int tid = threadIdx.x;   // 128 threads
    __shared__ int ws[4];
    int lane = tid & 31, wid = tid >> 5;
    int v = (tid < SCAN_NBLK) ? g_bsum[tid] : 0;
    int incl = v;
    #pragma unroll
    for (int o = 1; o < 32; o <<= 1) {
        int t = __shfl_up_sync(0xFFFFFFFFu, incl, o);
        if (lane >= o) incl += t;
    }
    if (lane == 31) ws[wid] = incl;
    __syncthreads();
    int woff = 0;
    #pragma unroll
    for (int k = 0; k < 4; ++k) woff += (k < wid) ? ws[k] : 0;
    if (tid < SCAN_NBLK) g_bsum[tid] = woff + incl - v;   // exclusive
    if (tid == 127) g_off[n] = woff + incl;               // grand total = NE
}

__global__ void k_scan3(int n) {
    int i = blockIdx.x * blockDim.x + threadIdx.x;
    if (i < n) g_off[i] += g_bsum[i >> 10];
}

__global__ void k_fill(const int* __restrict__ src, const int* __restrict__ dst, int E) {
    int e = blockIdx.x * blockDim.x + threadIdx.x;
    if (e < E) {
        int d = dst[e];
        int p = g_off[d] + atomicAdd(&g_cur[d], 1);
        g_csrc[p] = src[e];
    }
}

// ---------------- layer 1 (rank-3 path) --------------------------------------
__global__ void k_m1(const float* __restrict__ emb, const float* __restrict__ W1) {
    int r = blockIdx.x;            // 0..2
    int c = threadIdx.x;           // 0..511
    const float* er = emb + r * DIM;
    float acc = 0.f;
    for (int k = 0; k < DIM; ++k) acc = fmaf(er[k], W1[(size_t)k * DIM + c], acc);
    g_M1[r * DIM + c] = acc;
}

__global__ void k_wvec(const int* __restrict__ x, int n) {
    int d = blockIdx.x * blockDim.x + threadIdx.x;
    if (d >= n) return;
    float dv = g_dinv[d];
    float w[3] = {0.f, 0.f, 0.f};
    int e0 = g_off[d], e1 = g_off[d + 1];
    for (int e = e0; e < e1; ++e) {
        int s = g_csrc[e];
        w[x[s]] += g_dinv[s];
    }
    w[x[d]] += dv;
    float4 o;
    o.x = dv * w[0]; o.y = dv * w[1]; o.z = dv * w[2]; o.w = 0.f;
    *(float4*)&g_wvec[4 * (size_t)d] = o;
}

// ---------------- GEMM common pieces -----------------------------------------
#define BM 128
#define BN 128
#define BK 16
#define APITCHB 48
#define BPITCHB 272

// Fused layer-1 + GEMM-2: G = (relu(wvec@M1 + b1) @ W) * dinv[row]
__global__ void __launch_bounds__(256, 2)
k_gemm_l1(const float* __restrict__ W, const float* __restrict__ b1,
          uint16_t* __restrict__ G, int M) {
    __shared__ __align__(16) char As[2][BM * APITCHB];
    __shared__ __align__(16) char Bs[2][BK * BPITCHB];
    __shared__ float sM1[3][DIM];
    __shared__ float sB1[DIM];

    const int tid = threadIdx.x;
    const int lane = tid & 31;
    const int gid = lane >> 2;
    const int tig = lane & 3;
    const int warpId = tid >> 5;
    const int m0 = (warpId & 3) * 32;
    const int n0 = (warpId >> 2) * 64;

    const int rowBase = blockIdx.y * BM;
    const int colBase = blockIdx.x * BN;

    const int ar = tid >> 1;
    const int ah = tid & 1;
    const int arow = rowBase + ar;
    const bool aok = (arow < M);

    const int brow = tid >> 4;
    const int bc8 = (tid & 15) * 8;

    for (int i = tid; i < 3 * DIM; i += 256) ((float*)sM1)[i] = g_M1[i];
    for (int i = tid; i < DIM; i += 256) sB1[i] = b1[i];

    uint32_t asb[2], bsb[2];
    asb[0] = (uint32_t)__cvta_generic_to_shared(As[0]);
    asb[1] = (uint32_t)__cvta_generic_to_shared(As[1]);
    bsb[0] = (uint32_t)__cvta_generic_to_shared(Bs[0]);
    bsb[1] = (uint32_t)__cvta_generic_to_shared(Bs[1]);

    const uint32_t aoff = (uint32_t)(lane & 15) * APITCHB + (uint32_t)(lane >> 4) * 16;
    const uint32_t boff = (uint32_t)(lane & 15) * BPITCHB + (uint32_t)(lane >> 4) * 16;

    float4 wv = make_float4(0.f, 0.f, 0.f, 0.f);
    if (aok) wv = *(const float4*)&g_wvec[4 * (size_t)arow];

    float acc[2][8][4];
    #pragma unroll
    for (int i = 0; i < 2; ++i)
        #pragma unroll
        for (int j = 0; j < 8; ++j)
            #pragma unroll
            for (int k = 0; k < 4; ++k) acc[i][j][k] = 0.f;

    float4 pb0, pb1;
    {
        const float* wr = W + (size_t)brow * DIM + colBase + bc8;
        pb0 = *(const float4*)wr;
        pb1 = *(const float4*)(wr + 4);
    }
    __syncthreads();   // sM1/sB1 ready

    {
        int kb = ah * 8;
        float r[8];
        #pragma unroll
        for (int i = 0; i < 8; ++i) {
            float v = wv.x * sM1[0][kb + i] + wv.y * sM1[1][kb + i]
                    + wv.z * sM1[2][kb + i] + sB1[kb + i];
            r[i] = aok ? fmaxf(v, 0.f) : 0.f;
        }
        uint4 o;
        o.x = pack_bf16x2(r[0], r[1]);
        o.y = pack_bf16x2(r[2], r[3]);
        o.z = pack_bf16x2(r[4], r[5]);
        o.w = pack_bf16x2(r[6], r[7]);
        *(uint4*)(As[0] + ar * APITCHB + ah * 16) = o;
        uint4 v;
        v.x = pack_bf16x2(pb0.x, pb0.y);
        v.y = pack_bf16x2(pb0.z, pb0.w);
        v.z = pack_bf16x2(pb1.x, pb1.y);
        v.w = pack_bf16x2(pb1.z, pb1.w);
        *(uint4*)(Bs[0] + brow * BPITCHB + bc8 * 2) = v;
    }
    __syncthreads();

    const int NT = DIM / BK;
    int buf = 0;
    for (int t = 0; t < NT; ++t) {
        if (t + 1 < NT) {
            int k0 = (t + 1) * BK;
            const float* wr = W + (size_t)(k0 + brow) * DIM + colBase + bc8;
            pb0 = *(const float4*)wr;
            pb1 = *(const float4*)(wr + 4);
        }

        uint32_t af[2][4];
        #pragma unroll
        for (int mf = 0; mf < 2; ++mf)
            ldsm_x4(af[mf][0], af[mf][1], af[mf][2], af[mf][3],
                    asb[buf] + (uint32_t)(m0 + mf * 16) * APITCHB + aoff);

        #pragma unroll
        for (int p = 0; p < 4; ++p) {
            uint32_t b0, b1r, b2, b3;
            ldsm_x4_t(b0, b1r, b2, b3,
                      bsb[buf] + boff + (uint32_t)(n0 + p * 16) * 2);
            #pragma unroll
            for (int mf = 0; mf < 2; ++mf) {
                mma_bf16(acc[mf][2 * p],     af[mf], b0, b1r);
                mma_bf16(acc[mf][2 * p + 1], af[mf], b2, b3);
            }
        }

        if (t + 1 < NT) {
            buf ^= 1;
            int kb = (t + 1) * BK + ah * 8;
            float r[8];
            #pragma unroll
            for (int i = 0; i < 8; ++i) {
                float v = wv.x * sM1[0][kb + i] + wv.y * sM1[1][kb + i]
                        + wv.z * sM1[2][kb + i] + sB1[kb + i];
                r[i] = aok ? fmaxf(v, 0.f) : 0.f;
            }
            uint4 o;
            o.x = pack_bf16x2(r[0], r[1]);
            o.y = pack_bf16x2(r[2], r[3]);
            o.z = pack_bf16x2(r[4], r[5]);
            o.w = pack_bf16x2(r[6], r[7]);
            *(uint4*)(As[buf] + ar * APITCHB + ah * 16) = o;
            uint4 v;
            v.x = pack_bf16x2(pb0.x, pb0.y);
            v.y = pack_bf16x2(pb0.z, pb0.w);
            v.z = pack_bf16x2(pb1.x, pb1.y);
            v.w = pack_bf16x2(pb1.z, pb1.w);
            *(uint4*)(Bs[buf] + brow * BPITCHB + bc8 * 2) = v;
            __syncthreads();
        }
    }

    #pragma unroll
    for (int mf = 0; mf < 2; ++mf) {
        int r = rowBase + m0 + mf * 16 + gid;
        float dv0 = (r < M) ? g_dinv[r] : 0.f;
        float dv1 = (r + 8 < M) ? g_dinv[r + 8] : 0.f;
        #pragma unroll
        for (int nf = 0; nf < 8; ++nf) {
            int c = colBase + n0 + nf * 8 + 2 * tig;
            if (r < M)
                *(uint32_t*)(G + (size_t)r * DIM + c) =
                    pack_bf16x2(acc[mf][nf][0] * dv0, acc[mf][nf][1] * dv0);
            if (r + 8 < M)
                *(uint32_t*)(G + (size_t)(r + 8) * DIM + c) =
                    pack_bf16x2(acc[mf][nf][2] * dv1, acc[mf][nf][3] * dv1);
        }
    }
}

// Generic GEMM (layer 3): G = (A @ W) * dinv[row]
__global__ void __launch_bounds__(256, 2)
k_gemm(const uint16_t* __restrict__ A, const float* __restrict__ W,
       uint16_t* __restrict__ G, int M) {
    __shared__ __align__(16) char As[2][BM * APITCHB];
    __shared__ __align__(16) char Bs[2][BK * BPITCHB];

    const int tid = threadIdx.x;
    const int lane = tid & 31;
    const int gid = lane >> 2;
    const int tig = lane & 3;
    const int warpId = tid >> 5;
    const int m0 = (warpId & 3) * 32;
    const int n0 = (warpId >> 2) * 64;

    const int rowBase = blockIdx.y * BM;
    const int colBase = blockIdx.x * BN;

    const int ar = tid >> 1;
    const int ah = tid & 1;
    const int arow = rowBase + ar;
    const bool aok = (arow < M);
    const uint4* Ag = (const uint4*)(A + (size_t)arow * DIM);

    const int brow = tid >> 4;
    const int bc8 = (tid & 15) * 8;

    uint32_t asb[2], bsb[2];
    asb[0] = (uint32_t)__cvta_generic_to_shared(As[0]);
    asb[1] = (uint32_t)__cvta_generic_to_shared(As[1]);
    bsb[0] = (uint32_t)__cvta_generic_to_shared(Bs[0]);
    bsb[1] = (uint32_t)__cvta_generic_to_shared(Bs[1]);

    const uint32_t aoff = (uint32_t)(lane & 15) * APITCHB + (uint32_t)(lane >> 4) * 16;
    const uint32_t boff = (uint32_t)(lane & 15) * BPITCHB + (uint32_t)(lane >> 4) * 16;

    float acc[2][8][4];
    #pragma unroll
    for (int i = 0; i < 2; ++i)
        #pragma unroll
        for (int j = 0; j < 8; ++j)
            #pragma unroll
            for (int k = 0; k < 4; ++k) acc[i][j][k] = 0.f;

    uint4 pa;
    float4 pb0, pb1;

    pa = aok ? Ag[ah] : make_uint4(0, 0, 0, 0);
    {
        const float* wr = W + (size_t)brow * DIM + colBase + bc8;
        pb0 = *(const float4*)wr;
        pb1 = *(const float4*)(wr + 4);
    }
    *(uint4*)(As[0] + ar * APITCHB + ah * 16) = pa;
    {
        uint4 v;
        v.x = pack_bf16x2(pb0.x, pb0.y);
        v.y = pack_bf16x2(pb0.z, pb0.w);
        v.z = pack_bf16x2(pb1.x, pb1.y);
        v.w = pack_bf16x2(pb1.z, pb1.w);
        *(uint4*)(Bs[0] + brow * BPITCHB + bc8 * 2) = v;
    }
    __syncthreads();

    const int NT = DIM / BK;
    int buf = 0;
    for (int t = 0; t < NT; ++t) {
        if (t + 1 < NT) {
            int k0 = (t + 1) * BK;
            pa = aok ? Ag[(k0 >> 3) + ah] : make_uint4(0, 0, 0, 0);
            const float* wr = W + (size_t)(k0 + brow) * DIM + colBase + bc8;
            pb0 = *(const float4*)wr;
            pb1 = *(const float4*)(wr + 4);
        }

        uint32_t af[2][4];
        #pragma unroll
        for (int mf = 0; mf < 2; ++mf)
            ldsm_x4(af[mf][0], af[mf][1], af[mf][2], af[mf][3],
                    asb[buf] + (uint32_t)(m0 + mf * 16) * APITCHB + aoff);

        #pragma unroll
        for (int p = 0; p < 4; ++p) {
            uint32_t b0, b1, b2, b3;
            ldsm_x4_t(b0, b1, b2, b3,
                      bsb[buf] + boff + (uint32_t)(n0 + p * 16) * 2);
            #pragma unroll
            for (int mf = 0; mf < 2; ++mf) {
                mma_bf16(acc[mf][2 * p],     af[mf], b0, b1);
                mma_bf16(acc[mf][2 * p + 1], af[mf], b2, b3);
            }
        }

        if (t + 1 < NT) {
            buf ^= 1;
            *(uint4*)(As[buf] + ar * APITCHB + ah * 16) = pa;
            uint4 v;
            v.x = pack_bf16x2(pb0.x, pb0.y);
            v.y = pack_bf16x2(pb0.z, pb0.w);
            v.z = pack_bf16x2(pb1.x, pb1.y);
            v.w = pack_bf16x2(pb1.z, pb1.w);
            *(uint4*)(Bs[buf] + brow * BPITCHB + bc8 * 2) = v;
            __syncthreads();
        }
    }

    #pragma unroll
    for (int mf = 0; mf < 2; ++mf) {
        int r = rowBase + m0 + mf * 16 + gid;
        float dv0 = (r < M) ? g_dinv[r] : 0.f;
        float dv1 = (r + 8 < M) ? g_dinv[r + 8] : 0.f;
        #pragma unroll
        for (int nf = 0; nf < 8; ++nf) {
            int c = colBase + n0 + nf * 8 + 2 * tig;
            if (r < M)
                *(uint32_t*)(G + (size_t)r * DIM + c) =
                    pack_bf16x2(acc[mf][nf][0] * dv0, acc[mf][nf][1] * dv0);
            if (r + 8 < M)
                *(uint32_t*)(G + (size_t)(r + 8) * DIM + c) =
                    pack_bf16x2(acc[mf][nf][2] * dv1, acc[mf][nf][3] * dv1);
        }
    }
}

// ---------------- aggregation (layer 2): writes bf16 features ----------------
__global__ void k_agg(const uint16_t* __restrict__ G, const float* __restrict__ bias,
                      uint16_t* __restrict__ out, int n, int do_relu) {
    int w = (blockIdx.x * blockDim.x + threadIdx.x) >> 5;
    int lane = threadIdx.x & 31;
    if (w >= n) return;
    const uint4* G4 = (const uint4*)G;
    size_t base = (size_t)w * 64;

    float acc[16];
    #pragma unroll
    for (int j = 0; j < 2; ++j) {
        uint4 v = G4[base + lane + 32 * j];
        float2 f;
        f = unpack_bf16x2(v.x); acc[8 * j + 0] = f.x; acc[8 * j + 1] = f.y;
        f = unpack_bf16x2(v.y); acc[8 * j + 2] = f.x; acc[8 * j + 3] = f.y;
        f = unpack_bf16x2(v.z); acc[8 * j + 4] = f.x; acc[8 * j + 5] = f.y;
        f = unpack_bf16x2(v.w); acc[8 * j + 6] = f.x; acc[8 * j + 7] = f.y;
    }
    int e0 = g_off[w], e1 = g_off[w + 1];
    for (int e = e0; e < e1; ++e) {
        size_t sb = (size_t)g_csrc[e] * 64;
        #pragma unroll
        for (int j = 0; j < 2; ++j) {
            uint4 v = G4[sb + lane + 32 * j];
            float2 f;
            f = unpack_bf16x2(v.x); acc[8 * j + 0] += f.x; acc[8 * j + 1] += f.y;
            f = unpack_bf16x2(v.y); acc[8 * j + 2] += f.x; acc[8 * j + 3] += f.y;
            f = unpack_bf16x2(v.z); acc[8 * j + 4] += f.x; acc[8 * j + 5] += f.y;
            f = unpack_bf16x2(v.w); acc[8 * j + 6] += f.x; acc[8 * j + 7] += f.y;
        }
    }
    float d = g_dinv[w];
    uint4* O4 = (uint4*)out;
    const float4* B4 = (const float4*)bias;
    #pragma unroll
    for (int j = 0; j < 2; ++j) {
        int u = lane + 32 * j;
        float4 bb0 = B4[2 * u], bb1 = B4[2 * u + 1];
        float r[8];
        r[0] = acc[8 * j + 0] * d + bb0.x;
        r[1] = acc[8 * j + 1] * d + bb0.y;
        r[2] = acc[8 * j + 2] * d + bb0.z;
        r[3] = acc[8 * j + 3] * d + bb0.w;
        r[4] = acc[8 * j + 4] * d + bb1.x;
        r[5] = acc[8 * j + 5] * d + bb1.y;
        r[6] = acc[8 * j + 6] * d + bb1.z;
        r[7] = acc[8 * j + 7] * d + bb1.w;
        if (do_relu) {
            #pragma unroll
            for (int i = 0; i < 8; ++i) r[i] = fmaxf(r[i], 0.f);
        }
        uint4 v;
        v.x = pack_bf16x2(r[0], r[1]);
        v.y = pack_bf16x2(r[2], r[3]);
        v.z = pack_bf16x2(r[4], r[5]);
        v.w = pack_bf16x2(r[6], r[7]);
        O4[base + u] = v;
    }
}

// ---------------- layer-3 aggregation fused with layer-4 dot -----------------
// g_scal[w] = dinv[w] * ( relu(dinv*(g[w]+sum g[s]) + b3) . W4 )
__global__ void k_agg_dot(const uint16_t* __restrict__ G, const float* __restrict__ b3,
                          const float* __restrict__ W4, int n) {
    __shared__ float sW4[DIM];
    __shared__ float sB3[DIM];
    int tid = threadIdx.x;
    for (int i = tid; i < DIM; i += blockDim.x) { sW4[i] = W4[i]; sB3[i] = b3[i]; }
    __syncthreads();

    int w = (blockIdx.x * blockDim.x + tid) >> 5;
    int lane = tid & 31;
    if (w >= n) return;
    const uint4* G4 = (const uint4*)G;
    size_t base = (size_t)w * 64;

    float acc[16];
    #pragma unroll
    for (int j = 0; j < 2; ++j) {
        uint4 v = G4[base + lane + 32 * j];
        float2 f;
        f = unpack_bf16x2(v.x); acc[8 * j + 0] = f.x; acc[8 * j + 1] = f.y;
        f = unpack_bf16x2(v.y); acc[8 * j + 2] = f.x; acc[8 * j + 3] = f.y;
        f = unpack_bf16x2(v.z); acc[8 * j + 4] = f.x; acc[8 * j + 5] = f.y;
        f = unpack_bf16x2(v.w); acc[8 * j + 6] = f.x; acc[8 * j + 7] = f.y;
    }
    int e0 = g_off[w], e1 = g_off[w + 1];
    for (int e = e0; e < e1; ++e) {
        size_t sb = (size_t)g_csrc[e] * 64;
        #pragma unroll
        for (int j = 0; j < 2; ++j) {
            uint4 v = G4[sb + lane + 32 * j];
            float2 f;
            f = unpack_bf16x2(v.x); acc[8 * j + 0] += f.x; acc[8 * j + 1] += f.y;
            f = unpack_bf16x2(v.y); acc[8 * j + 2] += f.x; acc[8 * j + 3] += f.y;
            f = unpack_bf16x2(v.z); acc[8 * j + 4] += f.x; acc[8 * j + 5] += f.y;
            f = unpack_bf16x2(v.w); acc[8 * j + 6] += f.x; acc[8 * j + 7] += f.y;
        }
    }
    float d = g_dinv[w];
    float s = 0.f;
    #pragma unroll
    for (int j = 0; j < 2; ++j) {
        int c = 8 * (lane + 32 * j);
        #pragma unroll
        for (int i = 0; i < 8; ++i) {
            float h = fmaxf(acc[8 * j + i] * d + sB3[c + i], 0.f);
            s = fmaf(h, sW4[c + i], s);
        }
    }
    #pragma unroll
    for (int o = 16; o > 0; o >>= 1) s += __shfl_xor_sync(0xFFFFFFFFu, s, o);
    if (lane == 0) g_scal[w] = s * d;
}

__global__ void k_agg4(const float* __restrict__ b4, float* __restrict__ out, int n) {
    int i = blockIdx.x * blockDim.x + threadIdx.x;
    if (i >= n) return;
    float a = g_scal[i];
    int e0 = g_off[i], e1 = g_off[i + 1];
    for (int e = e0; e < e1; ++e) a += g_scal[g_csrc[e]];
    float v = g_dinv[i] * a + b4[0];
    out[i] = 1.f / (1.f + expf(-v));
}

// ---------------- launcher ---------------------------------------------------
extern "C" void kernel_launch(void* const* d_in, const int* in_sizes, int n_in,
                              void* d_out, int out_size) {
    const int*   x   = (const int*)d_in[0];
    const int*   ei  = (const int*)d_in[1];
    const float* emb = (const float*)d_in[2];
    const float* W1  = (const float*)d_in[3];
    const float* b1  = (const float*)d_in[4];
    const float* W2  = (const float*)d_in[5];
    const float* b2  = (const float*)d_in[6];
    const float* W3  = (const float*)d_in[7];
    const float* b3  = (const float*)d_in[8];
    const float* W4  = (const float*)d_in[9];
    const float* b4  = (const float*)d_in[10];
    float* out = (float*)d_out;

    int N = in_sizes[0];
    int E = in_sizes[1] / 2;
    const int* src = ei;
    const int* dst = ei + E;

    uint16_t *bufA, *bufG;
    cudaGetSymbolAddress((void**)&bufA, g_bufA);
    cudaGetSymbolAddress((void**)&bufG, g_bufG);
    int *cntp;
    cudaGetSymbolAddress((void**)&cntp, g_cnt);

    // graph preprocessing (g_cur zeroed inside k_scan1)
    cudaMemsetAsync(cntp, 0, (size_t)N * sizeof(int));
    k_count<<<(E + 255) / 256, 256>>>(dst, E);
    k_m1   <<<3, DIM>>>(emb, W1);
    k_scan1<<<SCAN_NBLK, SCAN_BLK>>>(N);
    k_scan2<<<1, 128>>>(N);
    k_scan3<<<(N + 1023) / 1024, 1024>>>(N);
    k_fill <<<(E + 255) / 256, 256>>>(src, dst, E);
    k_wvec <<<(N + 255) / 256, 256>>>(x, N);

    dim3 ggrid(DIM / BN, (N + BM - 1) / BM);
    int aggBlocks = (N + 7) / 8;

    // layer 1+2 fused GEMM, then aggregation
    k_gemm_l1<<<ggrid, 256>>>(W2, b1, bufG, N);
    k_agg    <<<aggBlocks, 256>>>(bufG, b2, bufA, N, 1);
    // layer 3 GEMM, then aggregation fused with layer-4 dot
    k_gemm   <<<ggrid, 256>>>(bufA, W3, bufG, N);
    k_agg_dot<<<aggBlocks, 256>>>(bufG, b3, W4, N);
    // layer 4 scalar aggregation + sigmoid
    k_agg4   <<<(N + 255) / 256, 256>>>(b4, out, N);
}

// round 16
// speedup vs baseline: 1.0705x; 1.0395x over previous
#include <cuda_runtime.h>
#include <cuda_bf16.h>
#include <math.h>
#include <stdint.h>

#define NN 100000
#define NE 400000
#define DIM 512

#define SCAN_BLK 1024
#define SCAN_NBLK ((NN + SCAN_BLK - 1) / SCAN_BLK)   // 98

// ---------------- scratch (static device globals; no allocations) -----------
__device__ __align__(16) uint16_t g_bufA[(size_t)NN * DIM];
__device__ __align__(16) uint16_t g_bufG[(size_t)NN * DIM];
__device__ float g_dinv[NN];
__device__ float g_scal[NN];
__device__ float g_wvec[(size_t)NN * 4];   // N x 3 class weights (padded to 4)
__device__ float g_M1[3 * DIM];            // emb @ W1 (accumulated via atomics)
__device__ int   g_cnt[NN];
__device__ int   g_cur[NN];
__device__ int   g_off[NN + 1];
__device__ int   g_bsum[SCAN_NBLK + 1];
__device__ int   g_csrc[NE];

// ---------------- helpers ----------------------------------------------------
__device__ __forceinline__ uint32_t pack_bf16x2(float lo, float hi) {
    __nv_bfloat162 h = __floats2bfloat162_rn(lo, hi);
    return *(uint32_t*)&h;
}
__device__ __forceinline__ float2 unpack_bf16x2(uint32_t u) {
    __nv_bfloat162 h = *(__nv_bfloat162*)&u;
    return __bfloat1622float2(h);
}

__device__ __forceinline__ void ldsm_x4(uint32_t& r0, uint32_t& r1, uint32_t& r2,
                                        uint32_t& r3, uint32_t addr) {
    asm volatile("ldmatrix.sync.aligned.m8n8.x4.shared.b16 {%0,%1,%2,%3}, [%4];"
                 : "=r"(r0), "=r"(r1), "=r"(r2), "=r"(r3) : "r"(addr));
}
__device__ __forceinline__ void ldsm_x4_t(uint32_t& r0, uint32_t& r1, uint32_t& r2,
                                          uint32_t& r3, uint32_t addr) {
    asm volatile("ldmatrix.sync.aligned.m8n8.x4.trans.shared.b16 {%0,%1,%2,%3}, [%4];"
                 : "=r"(r0), "=r"(r1), "=r"(r2), "=r"(r3) : "r"(addr));
}
__device__ __forceinline__ void mma_bf16(float* c, const uint32_t* a,
                                         uint32_t b0, uint32_t b1) {
    asm volatile(
        "mma.sync.aligned.m16n8k16.row.col.f32.bf16.bf16.f32 "
        "{%0,%1,%2,%3}, {%4,%5,%6,%7}, {%8,%9}, {%0,%1,%2,%3};"
        : "+f"(c[0]), "+f"(c[1]), "+f"(c[2]), "+f"(c[3])
        : "r"(a[0]), "r"(a[1]), "r"(a[2]), "r"(a[3]), "r"(b0), "r"(b1));
}

// ---------------- graph preprocessing ---------------------------------------
__global__ void k_count(const int* __restrict__ dst, int E) {
    int e = blockIdx.x * blockDim.x + threadIdx.x;
    if (e < E) atomicAdd(&g_cnt[dst[e]], 1);
}

__global__ void k_scan1(int n) {
    __shared__ int wsum[32];
    int tid = threadIdx.x, lane = tid & 31, wid = tid >> 5;
    int i = blockIdx.x * SCAN_BLK + tid;
    int v = (i < n) ? g_cnt[i] : 0;
    if (i < n) { g_dinv[i] = rsqrtf((float)(v + 1)); g_cur[i] = 0; }
    int incl = v;
    #pragma unroll
    for (int o = 1; o < 32; o <<= 1) {
        int t = __shfl_up_sync(0xFFFFFFFFu, incl, o);
        if (lane >= o) incl += t;
    }
    if (lane == 31) wsum[wid] = incl;
    __syncthreads();
    if (wid == 0) {
        int s = wsum[lane];
        int si = s;
        #pragma unroll
        for (int o = 1; o < 32; o <<= 1) {
            int t = __shfl_up_sync(0xFFFFFFFFu, si, o);
            if (lane >= o) si += t;
        }
        wsum[lane] = si - s;
        if (lane == 31) g_bsum[blockIdx.x] = si;   // block total
    }
    __syncthreads();
    if (i < n) g_off[i] = wsum[wid] + incl - v;
}

// merged scan2+scan3: each block reduces its own prefix of block sums
__global__ void k_scan3(int n, int E) {
    __shared__ int wr[4];
    __shared__ int pref;
    int tid = threadIdx.x, b = blockIdx.x;
    if (tid < 128) {
        int lane = tid & 31, wid = tid >> 5;
        int v = (tid < b) ? g_bsum[tid] : 0;   // b <= 97 < 128
        #pragma unroll
        for (int o = 16; o > 0; o >>= 1) v += __shfl_xor_sync(0xFFFFFFFFu, v, o);
        if (lane == 0) wr[wid] = v;
    }
    __syncthreads();
    if (tid == 0) pref = wr[0] + wr[1] + wr[2] + wr[3];
    __syncthreads();
    int i = b * SCAN_BLK + tid;
    if (i < n) g_off[i] += pref;
    if (b == 0 && tid == 0) g_off[n] = E;
}

__global__ void k_fill(const int* __restrict__ src, const int* __restrict__ dst, int E) {
    int e = blockIdx.x * blockDim.x + threadIdx.x;
    if (e < E) {
        int d = dst[e];
        int p = g_off[d] + atomicAdd(&g_cur[d], 1);
        g_csrc[p] = src[e];
    }
}

// ---------------- layer 1 (rank-3 path) --------------------------------------
// Parallel M1 = emb @ W1: 16 blocks split K; fp32 atomic accumulation.
__global__ void k_m1p(const float* __restrict__ emb, const float* __restrict__ W1) {
    int c = threadIdx.x;               // 0..511
    int k0 = blockIdx.x * 32;          // 16 blocks
    float a0 = 0.f, a1 = 0.f, a2 = 0.f;
    #pragma unroll 4
    for (int k = k0; k < k0 + 32; ++k) {
        float w = W1[(size_t)k * DIM + c];
        a0 = fmaf(emb[k], w, a0);
        a1 = fmaf(emb[DIM + k], w, a1);
        a2 = fmaf(emb[2 * DIM + k], w, a2);
    }
    atomicAdd(&g_M1[c], a0);
    atomicAdd(&g_M1[DIM + c], a1);
    atomicAdd(&g_M1[2 * DIM + c], a2);
}

__global__ void k_wvec(const int* __restrict__ x, int n) {
    int d = blockIdx.x * blockDim.x + threadIdx.x;
    if (d >= n) return;
    float dv = g_dinv[d];
    float w[3] = {0.f, 0.f, 0.f};
    int e0 = g_off[d], e1 = g_off[d + 1];
    for (int e = e0; e < e1; ++e) {
        int s = g_csrc[e];
        w[x[s]] += g_dinv[s];
    }
    w[x[d]] += dv;
    float4 o;
    o.x = dv * w[0]; o.y = dv * w[1]; o.z = dv * w[2]; o.w = 0.f;
    *(float4*)&g_wvec[4 * (size_t)d] = o;
}

// ---------------- GEMM common pieces -----------------------------------------
#define BM 128
#define BN 128
#define BK 16
#define APITCHB 48
#define BPITCHB 272

// Fused layer-1 + GEMM-2: G = (relu(wvec@M1 + b1) @ W) * dinv[row]
__global__ void __launch_bounds__(256, 2)
k_gemm_l1(const float* __restrict__ W, const float* __restrict__ b1,
          uint16_t* __restrict__ G, int M) {
    __shared__ __align__(16) char As[2][BM * APITCHB];
    __shared__ __align__(16) char Bs[2][BK * BPITCHB];
    __shared__ float sM1[3][DIM];
    __shared__ float sB1[DIM];

    const int tid = threadIdx.x;
    const int lane = tid & 31;
    const int gid = lane >> 2;
    const int tig = lane & 3;
    const int warpId = tid >> 5;
    const int m0 = (warpId & 3) * 32;
    const int n0 = (warpId >> 2) * 64;

    const int rowBase = blockIdx.y * BM;
    const int colBase = blockIdx.x * BN;

    const int ar = tid >> 1;
    const int ah = tid & 1;
    const int arow = rowBase + ar;
    const bool aok = (arow < M);

    const int brow = tid >> 4;
    const int bc8 = (tid & 15) * 8;

    for (int i = tid; i < 3 * DIM; i += 256) ((float*)sM1)[i] = g_M1[i];
    for (int i = tid; i < DIM; i += 256) sB1[i] = b1[i];

    uint32_t asb[2], bsb[2];
    asb[0] = (uint32_t)__cvta_generic_to_shared(As[0]);
    asb[1] = (uint32_t)__cvta_generic_to_shared(As[1]);
    bsb[0] = (uint32_t)__cvta_generic_to_shared(Bs[0]);
    bsb[1] = (uint32_t)__cvta_generic_to_shared(Bs[1]);

    const uint32_t aoff = (uint32_t)(lane & 15) * APITCHB + (uint32_t)(lane >> 4) * 16;
    const uint32_t boff = (uint32_t)(lane & 15) * BPITCHB + (uint32_t)(lane >> 4) * 16;

    float4 wv = make_float4(0.f, 0.f, 0.f, 0.f);
    if (aok) wv = *(const float4*)&g_wvec[4 * (size_t)arow];

    float acc[2][8][4];
    #pragma unroll
    for (int i = 0; i < 2; ++i)
        #pragma unroll
        for (int j = 0; j < 8; ++j)
            #pragma unroll
            for (int k = 0; k < 4; ++k) acc[i][j][k] = 0.f;

    float4 pb0, pb1;
    {
        const float* wr = W + (size_t)brow * DIM + colBase + bc8;
        pb0 = *(const float4*)wr;
        pb1 = *(const float4*)(wr + 4);
    }
    __syncthreads();   // sM1/sB1 ready

    {
        int kb = ah * 8;
        float r[8];
        #pragma unroll
        for (int i = 0; i < 8; ++i) {
            float v = wv.x * sM1[0][kb + i] + wv.y * sM1[1][kb + i]
                    + wv.z * sM1[2][kb + i] + sB1[kb + i];
            r[i] = aok ? fmaxf(v, 0.f) : 0.f;
        }
        uint4 o;
        o.x = pack_bf16x2(r[0], r[1]);
        o.y = pack_bf16x2(r[2], r[3]);
        o.z = pack_bf16x2(r[4], r[5]);
        o.w = pack_bf16x2(r[6], r[7]);
        *(uint4*)(As[0] + ar * APITCHB + ah * 16) = o;
        uint4 v;
        v.x = pack_bf16x2(pb0.x, pb0.y);
        v.y = pack_bf16x2(pb0.z, pb0.w);
        v.z = pack_bf16x2(pb1.x, pb1.y);
        v.w = pack_bf16x2(pb1.z, pb1.w);
        *(uint4*)(Bs[0] + brow * BPITCHB + bc8 * 2) = v;
    }
    __syncthreads();

    const int NT = DIM / BK;
    int buf = 0;
    for (int t = 0; t < NT; ++t) {
        if (t + 1 < NT) {
            int k0 = (t + 1) * BK;
            const float* wr = W + (size_t)(k0 + brow) * DIM + colBase + bc8;
            pb0 = *(const float4*)wr;
            pb1 = *(const float4*)(wr + 4);
        }

        uint32_t af[2][4];
        #pragma unroll
        for (int mf = 0; mf < 2; ++mf)
            ldsm_x4(af[mf][0], af[mf][1], af[mf][2], af[mf][3],
                    asb[buf] + (uint32_t)(m0 + mf * 16) * APITCHB + aoff);

        #pragma unroll
        for (int p = 0; p < 4; ++p) {
            uint32_t b0, b1r, b2, b3;
            ldsm_x4_t(b0, b1r, b2, b3,
                      bsb[buf] + boff + (uint32_t)(n0 + p * 16) * 2);
            #pragma unroll
            for (int mf = 0; mf < 2; ++mf) {
                mma_bf16(acc[mf][2 * p],     af[mf], b0, b1r);
                mma_bf16(acc[mf][2 * p + 1], af[mf], b2, b3);
            }
        }

        if (t + 1 < NT) {
            buf ^= 1;
            int kb = (t + 1) * BK + ah * 8;
            float r[8];
            #pragma unroll
            for (int i = 0; i < 8; ++i) {
                float v = wv.x * sM1[0][kb + i] + wv.y * sM1[1][kb + i]
                        + wv.z * sM1[2][kb + i] + sB1[kb + i];
                r[i] = aok ? fmaxf(v, 0.f) : 0.f;
            }
            uint4 o;
            o.x = pack_bf16x2(r[0], r[1]);
            o.y = pack_bf16x2(r[2], r[3]);
            o.z = pack_bf16x2(r[4], r[5]);
            o.w = pack_bf16x2(r[6], r[7]);
            *(uint4*)(As[buf] + ar * APITCHB + ah * 16) = o;
            uint4 v;
            v.x = pack_bf16x2(pb0.x, pb0.y);
            v.y = pack_bf16x2(pb0.z, pb0.w);
            v.z = pack_bf16x2(pb1.x, pb1.y);
            v.w = pack_bf16x2(pb1.z, pb1.w);
            *(uint4*)(Bs[buf] + brow * BPITCHB + bc8 * 2) = v;
            __syncthreads();
        }
    }

    #pragma unroll
    for (int mf = 0; mf < 2; ++mf) {
        int r = rowBase + m0 + mf * 16 + gid;
        float dv0 = (r < M) ? g_dinv[r] : 0.f;
        float dv1 = (r + 8 < M) ? g_dinv[r + 8] : 0.f;
        #pragma unroll
        for (int nf = 0; nf < 8; ++nf) {
            int c = colBase + n0 + nf * 8 + 2 * tig;
            if (r < M)
                *(uint32_t*)(G + (size_t)r * DIM + c) =
                    pack_bf16x2(acc[mf][nf][0] * dv0, acc[mf][nf][1] * dv0);
            if (r + 8 < M)
                *(uint32_t*)(G + (size_t)(r + 8) * DIM + c) =
                    pack_bf16x2(acc[mf][nf][2] * dv1, acc[mf][nf][3] * dv1);
        }
    }
}

// Generic GEMM (layer 3): G = (A @ W) * dinv[row]
__global__ void __launch_bounds__(256, 2)
k_gemm(const uint16_t* __restrict__ A, const float* __restrict__ W,
       uint16_t* __restrict__ G, int M) {
    __shared__ __align__(16) char As[2][BM * APITCHB];
    __shared__ __align__(16) char Bs[2][BK * BPITCHB];

    const int tid = threadIdx.x;
    const int lane = tid & 31;
    const int gid = lane >> 2;
    const int tig = lane & 3;
    const int warpId = tid >> 5;
    const int m0 = (warpId & 3) * 32;
    const int n0 = (warpId >> 2) * 64;

    const int rowBase = blockIdx.y * BM;
    const int colBase = blockIdx.x * BN;

    const int ar = tid >> 1;
    const int ah = tid & 1;
    const int arow = rowBase + ar;
    const bool aok = (arow < M);
    const uint4* Ag = (const uint4*)(A + (size_t)arow * DIM);

    const int brow = tid >> 4;
    const int bc8 = (tid & 15) * 8;

    uint32_t asb[2], bsb[2];
    asb[0] = (uint32_t)__cvta_generic_to_shared(As[0]);
    asb[1] = (uint32_t)__cvta_generic_to_shared(As[1]);
    bsb[0] = (uint32_t)__cvta_generic_to_shared(Bs[0]);
    bsb[1] = (uint32_t)__cvta_generic_to_shared(Bs[1]);

    const uint32_t aoff = (uint32_t)(lane & 15) * APITCHB + (uint32_t)(lane >> 4) * 16;
    const uint32_t boff = (uint32_t)(lane & 15) * BPITCHB + (uint32_t)(lane >> 4) * 16;

    float acc[2][8][4];
    #pragma unroll
    for (int i = 0; i < 2; ++i)
        #pragma unroll
        for (int j = 0; j < 8; ++j)
            #pragma unroll
            for (int k = 0; k < 4; ++k) acc[i][j][k] = 0.f;

    uint4 pa;
    float4 pb0, pb1;

    pa = aok ? Ag[ah] : make_uint4(0, 0, 0, 0);
    {
        const float* wr = W + (size_t)brow * DIM + colBase + bc8;
        pb0 = *(const float4*)wr;
        pb1 = *(const float4*)(wr + 4);
    }
    *(uint4*)(As[0] + ar * APITCHB + ah * 16) = pa;
    {
        uint4 v;
        v.x = pack_bf16x2(pb0.x, pb0.y);
        v.y = pack_bf16x2(pb0.z, pb0.w);
        v.z = pack_bf16x2(pb1.x, pb1.y);
        v.w = pack_bf16x2(pb1.z, pb1.w);
        *(uint4*)(Bs[0] + brow * BPITCHB + bc8 * 2) = v;
    }
    __syncthreads();

    const int NT = DIM / BK;
    int buf = 0;
    for (int t = 0; t < NT; ++t) {
        if (t + 1 < NT) {
            int k0 = (t + 1) * BK;
            pa = aok ? Ag[(k0 >> 3) + ah] : make_uint4(0, 0, 0, 0);
            const float* wr = W + (size_t)(k0 + brow) * DIM + colBase + bc8;
            pb0 = *(const float4*)wr;
            pb1 = *(const float4*)(wr + 4);
        }

        uint32_t af[2][4];
        #pragma unroll
        for (int mf = 0; mf < 2; ++mf)
            ldsm_x4(af[mf][0], af[mf][1], af[mf][2], af[mf][3],
                    asb[buf] + (uint32_t)(m0 + mf * 16) * APITCHB + aoff);

        #pragma unroll
        for (int p = 0; p < 4; ++p) {
            uint32_t b0, b1, b2, b3;
            ldsm_x4_t(b0, b1, b2, b3,
                      bsb[buf] + boff + (uint32_t)(n0 + p * 16) * 2);
            #pragma unroll
            for (int mf = 0; mf < 2; ++mf) {
                mma_bf16(acc[mf][2 * p],     af[mf], b0, b1);
                mma_bf16(acc[mf][2 * p + 1], af[mf], b2, b3);
            }
        }

        if (t + 1 < NT) {
            buf ^= 1;
            *(uint4*)(As[buf] + ar * APITCHB + ah * 16) = pa;
            uint4 v;
            v.x = pack_bf16x2(pb0.x, pb0.y);
            v.y = pack_bf16x2(pb0.z, pb0.w);
            v.z = pack_bf16x2(pb1.x, pb1.y);
            v.w = pack_bf16x2(pb1.z, pb1.w);
            *(uint4*)(Bs[buf] + brow * BPITCHB + bc8 * 2) = v;
            __syncthreads();
        }
    }

    #pragma unroll
    for (int mf = 0; mf < 2; ++mf) {
        int r = rowBase + m0 + mf * 16 + gid;
        float dv0 = (r < M) ? g_dinv[r] : 0.f;
        float dv1 = (r + 8 < M) ? g_dinv[r + 8] : 0.f;
        #pragma unroll
        for (int nf = 0; nf < 8; ++nf) {
            int c = colBase + n0 + nf * 8 + 2 * tig;
            if (r < M)
                *(uint32_t*)(G + (size_t)r * DIM + c) =
                    pack_bf16x2(acc[mf][nf][0] * dv0, acc[mf][nf][1] * dv0);
            if (r + 8 < M)
                *(uint32_t*)(G + (size_t)(r + 8) * DIM + c) =
                    pack_bf16x2(acc[mf][nf][2] * dv1, acc[mf][nf][3] * dv1);
        }
    }
}

// ---------------- aggregation (layer 2): writes bf16 features ----------------
__global__ void k_agg(const uint16_t* __restrict__ G, const float* __restrict__ bias,
                      uint16_t* __restrict__ out, int n, int do_relu) {
    int w = (blockIdx.x * blockDim.x + threadIdx.x) >> 5;
    int lane = threadIdx.x & 31;
    if (w >= n) return;
    const uint4* G4 = (const uint4*)G;
    size_t base = (size_t)w * 64;

    float acc[16];
    #pragma unroll
    for (int j = 0; j < 2; ++j) {
        uint4 v = G4[base + lane + 32 * j];
        float2 f;
        f = unpack_bf16x2(v.x); acc[8 * j + 0] = f.x; acc[8 * j + 1] = f.y;
        f = unpack_bf16x2(v.y); acc[8 * j + 2] = f.x; acc[8 * j + 3] = f.y;
        f = unpack_bf16x2(v.z); acc[8 * j + 4] = f.x; acc[8 * j + 5] = f.y;
        f = unpack_bf16x2(v.w); acc[8 * j + 6] = f.x; acc[8 * j + 7] = f.y;
    }
    int e0 = g_off[w], e1 = g_off[w + 1];
    for (int e = e0; e < e1; ++e) {
        size_t sb = (size_t)g_csrc[e] * 64;
        #pragma unroll
        for (int j = 0; j < 2; ++j) {
            uint4 v = G4[sb + lane + 32 * j];
            float2 f;
            f = unpack_bf16x2(v.x); acc[8 * j + 0] += f.x; acc[8 * j + 1] += f.y;
            f = unpack_bf16x2(v.y); acc[8 * j + 2] += f.x; acc[8 * j + 3] += f.y;
            f = unpack_bf16x2(v.z); acc[8 * j + 4] += f.x; acc[8 * j + 5] += f.y;
            f = unpack_bf16x2(v.w); acc[8 * j + 6] += f.x; acc[8 * j + 7] += f.y;
        }
    }
    float d = g_dinv[w];
    uint4* O4 = (uint4*)out;
    const float4* B4 = (const float4*)bias;
    #pragma unroll
    for (int j = 0; j < 2; ++j) {
        int u = lane + 32 * j;
        float4 bb0 = B4[2 * u], bb1 = B4[2 * u + 1];
        float r[8];
        r[0] = acc[8 * j + 0] * d + bb0.x;
        r[1] = acc[8 * j + 1] * d + bb0.y;
        r[2] = acc[8 * j + 2] * d + bb0.z;
        r[3] = acc[8 * j + 3] * d + bb0.w;
        r[4] = acc[8 * j + 4] * d + bb1.x;
        r[5] = acc[8 * j + 5] * d + bb1.y;
        r[6] = acc[8 * j + 6] * d + bb1.z;
        r[7] = acc[8 * j + 7] * d + bb1.w;
        if (do_relu) {
            #pragma unroll
            for (int i = 0; i < 8; ++i) r[i] = fmaxf(r[i], 0.f);
        }
        uint4 v;
        v.x = pack_bf16x2(r[0], r[1]);
        v.y = pack_bf16x2(r[2], r[3]);
        v.z = pack_bf16x2(r[4], r[5]);
        v.w = pack_bf16x2(r[6], r[7]);
        O4[base + u] = v;
    }
}

// ---------------- layer-3 aggregation fused with layer-4 dot -----------------
// g_scal[w] = dinv[w] * ( relu(dinv*(g[w]+sum g[s]) + b3) . W4 )
__global__ void k_agg_dot(const uint16_t* __restrict__ G, const float* __restrict__ b3,
                          const float* __restrict__ W4, int n) {
    __shared__ float sW4[DIM];
    __shared__ float sB3[DIM];
    int tid = threadIdx.x;
    for (int i = tid; i < DIM; i += blockDim.x) { sW4[i] = W4[i]; sB3[i] = b3[i]; }
    __syncthreads();

    int w = (blockIdx.x * blockDim.x + tid) >> 5;
    int lane = tid & 31;
    if (w >= n) return;
    const uint4* G4 = (const uint4*)G;
    size_t base = (size_t)w * 64;

    float acc[16];
    #pragma unroll
    for (int j = 0; j < 2; ++j) {
        uint4 v = G4[base + lane + 32 * j];
        float2 f;
        f = unpack_bf16x2(v.x); acc[8 * j + 0] = f.x; acc[8 * j + 1] = f.y;
        f = unpack_bf16x2(v.y); acc[8 * j + 2] = f.x; acc[8 * j + 3] = f.y;
        f = unpack_bf16x2(v.z); acc[8 * j + 4] = f.x; acc[8 * j + 5] = f.y;
        f = unpack_bf16x2(v.w); acc[8 * j + 6] = f.x; acc[8 * j + 7] = f.y;
    }
    int e0 = g_off[w], e1 = g_off[w + 1];
    for (int e = e0; e < e1; ++e) {
        size_t sb = (size_t)g_csrc[e] * 64;
        #pragma unroll
        for (int j = 0; j < 2; ++j) {
            uint4 v = G4[sb + lane + 32 * j];
            float2 f;
            f = unpack_bf16x2(v.x); acc[8 * j + 0] += f.x; acc[8 * j + 1] += f.y;
            f = unpack_bf16x2(v.y); acc[8 * j + 2] += f.x; acc[8 * j + 3] += f.y;
            f = unpack_bf16x2(v.z); acc[8 * j + 4] += f.x; acc[8 * j + 5] += f.y;
            f = unpack_bf16x2(v.w); acc[8 * j + 6] += f.x; acc[8 * j + 7] += f.y;
        }
    }
    float d = g_dinv[w];
    float s = 0.f;
    #pragma unroll
    for (int j = 0; j < 2; ++j) {
        int c = 8 * (lane + 32 * j);
        #pragma unroll
        for (int i = 0; i < 8; ++i) {
            float h = fmaxf(acc[8 * j + i] * d + sB3[c + i], 0.f);
            s = fmaf(h, sW4[c + i], s);
        }
    }
    #pragma unroll
    for (int o = 16; o > 0; o >>= 1) s += __shfl_xor_sync(0xFFFFFFFFu, s, o);
    if (lane == 0) g_scal[w] = s * d;
}

__global__ void k_agg4(const float* __restrict__ b4, float* __restrict__ out, int n) {
    int i = blockIdx.x * blockDim.x + threadIdx.x;
    if (i >= n) return;
    float a = g_scal[i];
    int e0 = g_off[i], e1 = g_off[i + 1];
    for (int e = e0; e < e1; ++e) a += g_scal[g_csrc[e]];
    float v = g_dinv[i] * a + b4[0];
    out[i] = 1.f / (1.f + expf(-v));
}

// ---------------- launcher ---------------------------------------------------
extern "C" void kernel_launch(void* const* d_in, const int* in_sizes, int n_in,
                              void* d_out, int out_size) {
    const int*   x   = (const int*)d_in[0];
    const int*   ei  = (const int*)d_in[1];
    const float* emb = (const float*)d_in[2];
    const float* W1  = (const float*)d_in[3];
    const float* b1  = (const float*)d_in[4];
    const float* W2  = (const float*)d_in[5];
    const float* b2  = (const float*)d_in[6];
    const float* W3  = (const float*)d_in[7];
    const float* b3  = (const float*)d_in[8];
    const float* W4  = (const float*)d_in[9];
    const float* b4  = (const float*)d_in[10];
    float* out = (float*)d_out;

    int N = in_sizes[0];
    int E = in_sizes[1] / 2;
    const int* src = ei;
    const int* dst = ei + E;

    uint16_t *bufA, *bufG;
    cudaGetSymbolAddress((void**)&bufA, g_bufA);
    cudaGetSymbolAddress((void**)&bufG, g_bufG);
    int *cntp;
    float *m1p;
    cudaGetSymbolAddress((void**)&cntp, g_cnt);
    cudaGetSymbolAddress((void**)&m1p, g_M1);

    // graph preprocessing (g_cur zeroed inside k_scan1; g_M1 accumulated)
    cudaMemsetAsync(cntp, 0, (size_t)N * sizeof(int));
    cudaMemsetAsync(m1p, 0, 3 * DIM * sizeof(float));
    k_count<<<(E + 255) / 256, 256>>>(dst, E);
    k_m1p  <<<16, DIM>>>(emb, W1);
    k_scan1<<<SCAN_NBLK, SCAN_BLK>>>(N);
    k_scan3<<<SCAN_NBLK, SCAN_BLK>>>(N, E);
    k_fill <<<(E + 255) / 256, 256>>>(src, dst, E);
    k_wvec <<<(N + 255) / 256, 256>>>(x, N);

    dim3 ggrid(DIM / BN, (N + BM - 1) / BM);
    int aggBlocks = (N + 7) / 8;

    // layer 1+2 fused GEMM, then aggregation
    k_gemm_l1<<<ggrid, 256>>>(W2, b1, bufG, N);
    k_agg    <<<aggBlocks, 256>>>(bufG, b2, bufA, N, 1);
    // layer 3 GEMM, then aggregation fused with layer-4 dot
    k_gemm   <<<ggrid, 256>>>(bufA, W3, bufG, N);
    k_agg_dot<<<aggBlocks, 256>>>(bufG, b3, W4, N);
    // layer 4 scalar aggregation + sigmoid
    k_agg4   <<<(N + 255) / 256, 256>>>(b4, out, N);
}